// round 13
// baseline (speedup 1.0000x reference)
#include <cuda_runtime.h>
#include <cuda_bf16.h>
#include <cstdint>

#define VOCAB 500000
#define DIM 128
#define RANK 8
#define SCALING 2.0f
#define RANK_THRESHOLD 0.1f

#define NWARPS 8
#define STAGES 8
#define CHUNK 64              // (direct fallback path)

#define NBUCK 1024
#define BUCK_SHIFT 9          // bucket = idx >> 9
#define CAP 2048              // slots per bucket region (expected fill ~840)
#define MAXTOK (1 << 20)
#define SCHUNK 2048           // tokens per scatter block

// ---- scratch (static; no allocation). Invariants restored every execution:
// g_cnt[] == 0, g_ovf_cnt == 0 at kernel_launch entry.
__device__ int  g_cnt[NBUCK];
__device__ int  g_ovf_cnt;
__device__ int2 g_bsort[NBUCK * CAP];   // bucketed (pos, idx)
__device__ int2 g_ovf[MAXTOK];          // overflow (pos, idx)

__device__ __forceinline__ void cp_async16(uint32_t smem_addr, const void* gptr) {
    asm volatile("cp.async.cg.shared.global [%0], [%1], 16;\n"
                 :: "r"(smem_addr), "l"(gptr));
}
__device__ __forceinline__ void cp_commit() {
    asm volatile("cp.async.commit_group;\n");
}

// ---- packed f32x2 helpers ----
__device__ __forceinline__ uint64_t pack2(float lo, float hi) {
    uint64_t r; asm("mov.b64 %0, {%1, %2};" : "=l"(r) : "f"(lo), "f"(hi)); return r;
}
__device__ __forceinline__ uint64_t bcast2(float v) {
    uint64_t r; asm("mov.b64 %0, {%1, %1};" : "=l"(r) : "f"(v)); return r;
}
__device__ __forceinline__ uint64_t fma2(uint64_t a, uint64_t b, uint64_t c) {
    uint64_t d; asm("fma.rn.f32x2 %0, %1, %2, %3;" : "=l"(d) : "l"(a), "l"(b), "l"(c)); return d;
}
__device__ __forceinline__ void unpack2(uint64_t v, float& lo, float& hi) {
    asm("mov.b64 {%0, %1}, %2;" : "=f"(lo), "=f"(hi) : "l"(v));
}

__device__ __forceinline__ bool detect_is64(const void* xv) {
    const long long* x64 = reinterpret_cast<const long long*>(xv);
    long long probe = x64[threadIdx.x & 31];
    bool bad = (probe < 0) || (probe >= (long long)VOCAB);
    return (__ballot_sync(0xFFFFFFFFu, bad) == 0u);
}

// shared LoRA math: o = e + sum_r b[r] * a2[r]
__device__ __forceinline__ float4 lora_apply(float4 e, float4 b0, float4 b1,
                                             const uint64_t a2[RANK][2]) {
    uint64_t o0 = pack2(e.x, e.y);
    uint64_t o1 = pack2(e.z, e.w);
    uint64_t bb;
    bb = bcast2(b0.x); o0 = fma2(bb, a2[0][0], o0); o1 = fma2(bb, a2[0][1], o1);
    bb = bcast2(b0.y); o0 = fma2(bb, a2[1][0], o0); o1 = fma2(bb, a2[1][1], o1);
    bb = bcast2(b0.z); o0 = fma2(bb, a2[2][0], o0); o1 = fma2(bb, a2[2][1], o1);
    bb = bcast2(b0.w); o0 = fma2(bb, a2[3][0], o0); o1 = fma2(bb, a2[3][1], o1);
    bb = bcast2(b1.x); o0 = fma2(bb, a2[4][0], o0); o1 = fma2(bb, a2[4][1], o1);
    bb = bcast2(b1.y); o0 = fma2(bb, a2[5][0], o0); o1 = fma2(bb, a2[5][1], o1);
    bb = bcast2(b1.z); o0 = fma2(bb, a2[6][0], o0); o1 = fma2(bb, a2[6][1], o1);
    bb = bcast2(b1.w); o0 = fma2(bb, a2[7][0], o0); o1 = fma2(bb, a2[7][1], o1);
    float4 o;
    unpack2(o0, o.x, o.y);
    unpack2(o1, o.z, o.w);
    return o;
}

__device__ __forceinline__ void load_a2(const float* A, const float* rp,
                                        int lane, uint64_t a2[RANK][2]) {
#pragma unroll
    for (int r = 0; r < RANK; r++) {
        float g = (rp[r] > RANK_THRESHOLD) ? SCALING : 0.0f;
        float4 av = reinterpret_cast<const float4*>(A)[r * (DIM / 4) + lane];
        a2[r][0] = pack2(av.x * g, av.y * g);
        a2[r][1] = pack2(av.z * g, av.w * g);
    }
}

// ---------------- single-pass bucketing scatter ----------------
__global__ void __launch_bounds__(256)
scatter_kernel(const void* __restrict__ xv, int ntok) {
    __shared__ int s_cnt[NBUCK];
    __shared__ int s_base[NBUCK];

    const bool is64 = detect_is64(xv);
    const long long* x64 = reinterpret_cast<const long long*>(xv);
    const int*       x32 = reinterpret_cast<const int*>(xv);

    const int start = blockIdx.x * SCHUNK;
    const int end   = min(start + SCHUNK, ntok);

    for (int i = threadIdx.x; i < NBUCK; i += blockDim.x) s_cnt[i] = 0;
    __syncthreads();

    // pass 1: local histogram (batched loads for MLP)
#pragma unroll 4
    for (int t = start + threadIdx.x; t < end; t += blockDim.x) {
        uint32_t idx = is64 ? (uint32_t)x64[t] : (uint32_t)x32[t];
        atomicAdd(&s_cnt[idx >> BUCK_SHIFT], 1);
    }
    __syncthreads();

    // reserve global slots (one atomic per non-empty bucket per block)
    for (int b = threadIdx.x; b < NBUCK; b += blockDim.x)
        s_base[b] = s_cnt[b] ? atomicAdd(&g_cnt[b], s_cnt[b]) : 0;
    __syncthreads();

    // pass 2: rank + write into bucket region (or overflow)
#pragma unroll 4
    for (int t = start + threadIdx.x; t < end; t += blockDim.x) {
        uint32_t idx = is64 ? (uint32_t)x64[t] : (uint32_t)x32[t];
        int b = idx >> BUCK_SHIFT;
        int p = atomicAdd(&s_base[b], 1);
        if (p < CAP) g_bsort[b * CAP + p] = make_int2(t, (int)idx);
        else {
            int q = atomicAdd(&g_ovf_cnt, 1);
            g_ovf[q] = make_int2(t, (int)idx);
        }
    }
}

// ---------------- main embed kernel: one block per bucket ----------------
__global__ void __launch_bounds__(NWARPS * 32)
cora_embed_kernel(const float* __restrict__ E,
                  const float* __restrict__ A,
                  const float* __restrict__ Bm,
                  const float* __restrict__ rp,
                  float* __restrict__ out)
{
    __shared__ float e_buf[NWARPS][STAGES][DIM];
    __shared__ float b_buf[NWARPS][STAGES][RANK];
    __shared__ int   s_n;

    const int lane = threadIdx.x & 31;
    const int w    = threadIdx.x >> 5;
    const int bkt  = blockIdx.x;

    if (threadIdx.x == 0) {
        s_n = min(g_cnt[bkt], CAP);
        g_cnt[bkt] = 0;                     // restore invariant for replay
    }
    __syncthreads();
    const int cnt = s_n;
    if (cnt == 0) return;

    uint64_t a2[RANK][2];
    load_a2(A, rp, lane, a2);

    const int per  = (cnt + NWARPS - 1) / NWARPS;
    const int beg  = w * per;
    if (beg >= cnt) return;
    const int nt   = min(per, cnt - beg);
    const int2* src = &g_bsort[(size_t)bkt * CAP + beg];

    const uint32_t e_base = (uint32_t)__cvta_generic_to_shared(&e_buf[w][0][0]);
    const uint32_t b_base = (uint32_t)__cvta_generic_to_shared(&b_buf[w][0][0]);

#pragma unroll
    for (int s = 0; s < STAGES; s++) {
        if (s < nt) {
            uint32_t idx = (uint32_t)src[s].y;
            cp_async16(e_base + (uint32_t)(s * DIM + lane * 4) * 4,
                       E + (size_t)idx * DIM + lane * 4);
            if (lane < 2)
                cp_async16(b_base + (uint32_t)(s * RANK + lane * 4) * 4,
                           Bm + (size_t)idx * RANK + lane * 4);
        }
        cp_commit();
    }

    for (int i = 0; i < nt; i++) {
        asm volatile("cp.async.wait_group %0;\n" :: "n"(STAGES - 1));
        __syncwarp();

        const int s = i & (STAGES - 1);
        float4 e  = *reinterpret_cast<const float4*>(&e_buf[w][s][lane * 4]);
        float4 b0 = *reinterpret_cast<const float4*>(&b_buf[w][s][0]);
        float4 b1 = *reinterpret_cast<const float4*>(&b_buf[w][s][4]);

        __syncwarp();

        int j = i + STAGES;
        if (j < nt) {
            uint32_t idx = (uint32_t)src[j].y;
            cp_async16(e_base + (uint32_t)(s * DIM + lane * 4) * 4,
                       E + (size_t)idx * DIM + lane * 4);
            if (lane < 2)
                cp_async16(b_base + (uint32_t)(s * RANK + lane * 4) * 4,
                           Bm + (size_t)idx * RANK + lane * 4);
        }
        cp_commit();

        float4 o = lora_apply(e, b0, b1, a2);
        int pos = src[i].x;
        __stcs(reinterpret_cast<float4*>(out + (size_t)pos * DIM) + lane, o);
    }
}

// ---------------- overflow cleanup (cold path; usually empty) ----------------
__global__ void __launch_bounds__(256)
overflow_kernel(const float* __restrict__ E, const float* __restrict__ A,
                const float* __restrict__ Bm, const float* __restrict__ rp,
                float* __restrict__ out)
{
    const int lane = threadIdx.x & 31;
    const int w    = threadIdx.x >> 5;
    const int n = g_ovf_cnt;
    if (n > 0) {
        uint64_t a2[RANK][2];
        load_a2(A, rp, lane, a2);
        for (int i = w; i < n; i += 8) {
            int2 pi = g_ovf[i];
            uint32_t idx = (uint32_t)pi.y;
            float4 e  = __ldg(reinterpret_cast<const float4*>(E + (size_t)idx * DIM) + lane);
            float4 b0 = __ldg(reinterpret_cast<const float4*>(Bm + (size_t)idx * RANK));
            float4 b1 = __ldg(reinterpret_cast<const float4*>(Bm + (size_t)idx * RANK) + 1);
            float4 o = lora_apply(e, b0, b1, a2);
            __stcs(reinterpret_cast<float4*>(out + (size_t)pi.x * DIM) + lane, o);
        }
    }
    __syncthreads();
    if (threadIdx.x == 0) g_ovf_cnt = 0;   // restore invariant
}

// ---------------- fallback (direct order) ----------------
__global__ void __launch_bounds__(NWARPS * 32)
cora_embed_direct(const void* __restrict__ xv,
                  const float* __restrict__ E, const float* __restrict__ A,
                  const float* __restrict__ Bm, const float* __restrict__ rp,
                  float* __restrict__ out, int ntok)
{
    __shared__ float e_buf[NWARPS][STAGES][DIM];
    __shared__ float b_buf[NWARPS][STAGES][RANK];
    const int lane = threadIdx.x & 31;
    const int w    = threadIdx.x >> 5;
    const int warp_global = blockIdx.x * NWARPS + w;
    const bool is64 = (ntok >= 64) ? detect_is64(xv) : false;
    const long long* x64 = reinterpret_cast<const long long*>(xv);
    const int*       x32 = reinterpret_cast<const int*>(xv);

    uint64_t a2[RANK][2];
    load_a2(A, rp, lane, a2);

    const int base = warp_global * CHUNK;
    if (base >= ntok) return;
    const int tend = min(base + CHUNK, ntok);
    const int nt = tend - base;
    const uint32_t e_base = (uint32_t)__cvta_generic_to_shared(&e_buf[w][0][0]);
    const uint32_t b_base = (uint32_t)__cvta_generic_to_shared(&b_buf[w][0][0]);
#pragma unroll
    for (int s = 0; s < STAGES; s++) {
        int t = base + s;
        if (t < tend) {
            uint32_t idx = is64 ? (uint32_t)x64[t] : (uint32_t)x32[t];
            cp_async16(e_base + (uint32_t)(s * DIM + lane * 4) * 4,
                       E + (size_t)idx * DIM + lane * 4);
            if (lane < 2)
                cp_async16(b_base + (uint32_t)(s * RANK + lane * 4) * 4,
                           Bm + (size_t)idx * RANK + lane * 4);
        }
        cp_commit();
    }
    for (int i = 0; i < nt; i++) {
        asm volatile("cp.async.wait_group %0;\n" :: "n"(STAGES - 1));
        __syncwarp();
        const int s = i & (STAGES - 1);
        float4 e  = *reinterpret_cast<const float4*>(&e_buf[w][s][lane * 4]);
        float4 b0 = *reinterpret_cast<const float4*>(&b_buf[w][s][0]);
        float4 b1 = *reinterpret_cast<const float4*>(&b_buf[w][s][4]);
        __syncwarp();
        int t = base + i + STAGES;
        if (t < tend) {
            uint32_t idx = is64 ? (uint32_t)x64[t] : (uint32_t)x32[t];
            cp_async16(e_base + (uint32_t)(s * DIM + lane * 4) * 4,
                       E + (size_t)idx * DIM + lane * 4);
            if (lane < 2)
                cp_async16(b_base + (uint32_t)(s * RANK + lane * 4) * 4,
                           Bm + (size_t)idx * RANK + lane * 4);
        }
        cp_commit();
        float4 o = lora_apply(e, b0, b1, a2);
        __stcs(reinterpret_cast<float4*>(out + (size_t)(base + i) * DIM) + lane, o);
    }
}

extern "C" void kernel_launch(void* const* d_in, const int* in_sizes, int n_in,
                              void* d_out, int out_size)
{
    const void*  x  = d_in[0];
    const float* E  = (const float*)d_in[1];
    const float* A  = (const float*)d_in[2];
    const float* Bm = (const float*)d_in[3];
    const float* rp = (const float*)d_in[4];
    float* out = (float*)d_out;

    const int ntok = out_size / DIM;

    if (ntok <= MAXTOK && ntok >= 64) {
        int sblocks = (ntok + SCHUNK - 1) / SCHUNK;
        scatter_kernel<<<sblocks, 256>>>(x, ntok);
        cora_embed_kernel<<<NBUCK, NWARPS * 32>>>(E, A, Bm, rp, out);
        overflow_kernel<<<1, 256>>>(E, A, Bm, rp, out);
    } else {
        int blocks = (ntok + NWARPS * CHUNK - 1) / (NWARPS * CHUNK);
        cora_embed_direct<<<blocks, NWARPS * 32>>>(x, E, A, Bm, rp, out, ntok);
    }
}

// round 14
// speedup vs baseline: 1.1316x; 1.1316x over previous
#include <cuda_runtime.h>
#include <cuda_bf16.h>
#include <cstdint>

#define VOCAB 500000
#define DIM 128
#define RANK 8
#define SCALING 2.0f
#define RANK_THRESHOLD 0.1f

#define NWARPS 8          // warps per block (256 threads)
#define STAGES 8          // cp.async pipeline depth (tokens in flight per warp)
#define CHUNK 64          // tokens per warp chunk (small chunks + multi-wave balancing)

__device__ __forceinline__ void cp_async16(uint32_t smem_addr, const void* gptr) {
    asm volatile("cp.async.cg.shared.global [%0], [%1], 16;\n"
                 :: "r"(smem_addr), "l"(gptr));
}
__device__ __forceinline__ void cp_commit() {
    asm volatile("cp.async.commit_group;\n");
}

// ---- packed f32x2 helpers (FFMA2 is only reachable via PTX fma.rn.f32x2) ----
__device__ __forceinline__ uint64_t pack2(float lo, float hi) {
    uint64_t r; asm("mov.b64 %0, {%1, %2};" : "=l"(r) : "f"(lo), "f"(hi)); return r;
}
__device__ __forceinline__ uint64_t bcast2(float v) {
    uint64_t r; asm("mov.b64 %0, {%1, %1};" : "=l"(r) : "f"(v)); return r;
}
__device__ __forceinline__ uint64_t fma2(uint64_t a, uint64_t b, uint64_t c) {
    uint64_t d; asm("fma.rn.f32x2 %0, %1, %2, %3;" : "=l"(d) : "l"(a), "l"(b), "l"(c)); return d;
}
__device__ __forceinline__ void unpack2(uint64_t v, float& lo, float& hi) {
    asm("mov.b64 {%0, %1}, %2;" : "=f"(lo), "=f"(hi) : "l"(v));
}

__global__ void __launch_bounds__(NWARPS * 32)
cora_embed_kernel(const void* __restrict__ xv,
                  const float* __restrict__ E,     // [VOCAB, 128]
                  const float* __restrict__ A,     // [8, 128]
                  const float* __restrict__ Bm,    // [VOCAB, 8]
                  const float* __restrict__ rp,    // [8]
                  float* __restrict__ out,         // [ntok, 128]
                  int ntok)
{
    __shared__ float e_buf[NWARPS][STAGES][DIM];   // 32 KB
    __shared__ float b_buf[NWARPS][STAGES][RANK];  // 2 KB

    const int lane = threadIdx.x & 31;
    const int w    = threadIdx.x >> 5;
    const int warp_global = blockIdx.x * NWARPS + w;

    // ---- inline index-dtype detection ----
    // All warps read the same first 32 int64 slots (one L2 line set, broadcast).
    // If data is int32, an int64 view is >= 2^32 unless the paired odd word is 0
    // (P ~ (1/VOCAB)^32 across 32 samples ~= 0).
    const long long* x64 = reinterpret_cast<const long long*>(xv);
    const int*       x32 = reinterpret_cast<const int*>(xv);
    long long probe = x64[lane];
    bool bad = (probe < 0) || (probe >= (long long)VOCAB);
    const bool is64 = (__ballot_sync(0xFFFFFFFFu, bad) == 0u);

    // Gated+scaled A columns for this lane's 4 dims, packed as f32x2 pairs.
    uint64_t a2[RANK][2];
#pragma unroll
    for (int r = 0; r < RANK; r++) {
        float g = (rp[r] > RANK_THRESHOLD) ? SCALING : 0.0f;
        float4 av = reinterpret_cast<const float4*>(A)[r * (DIM / 4) + lane];
        a2[r][0] = pack2(av.x * g, av.y * g);
        a2[r][1] = pack2(av.z * g, av.w * g);
    }

    const int base = warp_global * CHUNK;
    if (base >= ntok) return;
    const int tend = min(base + CHUNK, ntok);
    const int nt = tend - base;

    const uint32_t e_base = (uint32_t)__cvta_generic_to_shared(&e_buf[w][0][0]);
    const uint32_t b_base = (uint32_t)__cvta_generic_to_shared(&b_buf[w][0][0]);

    // ---------------- prologue: fill pipeline ----------------
#pragma unroll
    for (int s = 0; s < STAGES; s++) {
        int t = base + s;
        if (t < tend) {
            uint32_t idx = is64 ? (uint32_t)x64[t] : (uint32_t)x32[t];
            cp_async16(e_base + (uint32_t)(s * DIM + lane * 4) * 4,
                       E + (size_t)idx * DIM + lane * 4);
            if (lane < 2)
                cp_async16(b_base + (uint32_t)(s * RANK + lane * 4) * 4,
                           Bm + (size_t)idx * RANK + lane * 4);
        }
        cp_commit();
    }

    // ---------------- steady state ----------------
    for (int i = 0; i < nt; i++) {
        asm volatile("cp.async.wait_group %0;\n" :: "n"(STAGES - 1));
        __syncwarp();   // make lanes 0/1's B copies visible to all lanes

        const int s = i & (STAGES - 1);
        float4 e  = *reinterpret_cast<const float4*>(&e_buf[w][s][lane * 4]);
        float4 b0 = *reinterpret_cast<const float4*>(&b_buf[w][s][0]);
        float4 b1 = *reinterpret_cast<const float4*>(&b_buf[w][s][4]);

        __syncwarp();   // all lanes done reading stage s before refill

        int t = base + i + STAGES;
        if (t < tend) {
            uint32_t idx = is64 ? (uint32_t)x64[t] : (uint32_t)x32[t];
            cp_async16(e_base + (uint32_t)(s * DIM + lane * 4) * 4,
                       E + (size_t)idx * DIM + lane * 4);
            if (lane < 2)
                cp_async16(b_base + (uint32_t)(s * RANK + lane * 4) * 4,
                           Bm + (size_t)idx * RANK + lane * 4);
        }
        cp_commit();

        // packed f32x2 math: 16 FFMA2 + 8 broadcasts instead of 32 FFMA
        uint64_t o0 = pack2(e.x, e.y);
        uint64_t o1 = pack2(e.z, e.w);
        uint64_t bb;
        bb = bcast2(b0.x); o0 = fma2(bb, a2[0][0], o0); o1 = fma2(bb, a2[0][1], o1);
        bb = bcast2(b0.y); o0 = fma2(bb, a2[1][0], o0); o1 = fma2(bb, a2[1][1], o1);
        bb = bcast2(b0.z); o0 = fma2(bb, a2[2][0], o0); o1 = fma2(bb, a2[2][1], o1);
        bb = bcast2(b0.w); o0 = fma2(bb, a2[3][0], o0); o1 = fma2(bb, a2[3][1], o1);
        bb = bcast2(b1.x); o0 = fma2(bb, a2[4][0], o0); o1 = fma2(bb, a2[4][1], o1);
        bb = bcast2(b1.y); o0 = fma2(bb, a2[5][0], o0); o1 = fma2(bb, a2[5][1], o1);
        bb = bcast2(b1.z); o0 = fma2(bb, a2[6][0], o0); o1 = fma2(bb, a2[6][1], o1);
        bb = bcast2(b1.w); o0 = fma2(bb, a2[7][0], o0); o1 = fma2(bb, a2[7][1], o1);

        float4 o;
        unpack2(o0, o.x, o.y);
        unpack2(o1, o.z, o.w);

        __stcs(reinterpret_cast<float4*>(out + (size_t)(base + i) * DIM) + lane, o);
    }
}

extern "C" void kernel_launch(void* const* d_in, const int* in_sizes, int n_in,
                              void* d_out, int out_size)
{
    const void*  x  = d_in[0];                // [B, L] int32 or int64
    const float* E  = (const float*)d_in[1];  // [VOCAB, 128]
    const float* A  = (const float*)d_in[2];  // [8, 128]
    const float* Bm = (const float*)d_in[3];  // [VOCAB, 8]
    const float* rp = (const float*)d_in[4];  // [8]
    float* out = (float*)d_out;

    const int ntok = out_size / DIM;

    const int tok_per_block = NWARPS * CHUNK;                // 512
    int blocks = (ntok + tok_per_block - 1) / tok_per_block; // 1600
    cora_embed_kernel<<<blocks, NWARPS * 32>>>(x, E, A, Bm, rp, out, ntok);
}

// round 15
// speedup vs baseline: 1.1623x; 1.0271x over previous
#include <cuda_runtime.h>
#include <cuda_bf16.h>
#include <cstdint>

#define VOCAB 500000
#define DIM 128
#define RANK 8
#define SCALING 2.0f
#define RANK_THRESHOLD 0.1f

#define NWARPS 8          // warps per block (256 threads)
#define STAGES 8          // cp.async pipeline depth (tokens in flight per warp)
#define CHUNK 32          // tokens per warp chunk (shorter CTA lifetime -> smaller tail drain)

__device__ __forceinline__ void cp_async16(uint32_t smem_addr, const void* gptr) {
    asm volatile("cp.async.cg.shared.global [%0], [%1], 16;\n"
                 :: "r"(smem_addr), "l"(gptr));
}
__device__ __forceinline__ void cp_commit() {
    asm volatile("cp.async.commit_group;\n");
}

// ---- packed f32x2 helpers (FFMA2 is only reachable via PTX fma.rn.f32x2) ----
__device__ __forceinline__ uint64_t pack2(float lo, float hi) {
    uint64_t r; asm("mov.b64 %0, {%1, %2};" : "=l"(r) : "f"(lo), "f"(hi)); return r;
}
__device__ __forceinline__ uint64_t bcast2(float v) {
    uint64_t r; asm("mov.b64 %0, {%1, %1};" : "=l"(r) : "f"(v)); return r;
}
__device__ __forceinline__ uint64_t fma2(uint64_t a, uint64_t b, uint64_t c) {
    uint64_t d; asm("fma.rn.f32x2 %0, %1, %2, %3;" : "=l"(d) : "l"(a), "l"(b), "l"(c)); return d;
}
__device__ __forceinline__ void unpack2(uint64_t v, float& lo, float& hi) {
    asm("mov.b64 {%0, %1}, %2;" : "=f"(lo), "=f"(hi) : "l"(v));
}

__global__ void __launch_bounds__(NWARPS * 32)
cora_embed_kernel(const void* __restrict__ xv,
                  const float* __restrict__ E,     // [VOCAB, 128]
                  const float* __restrict__ A,     // [8, 128]
                  const float* __restrict__ Bm,    // [VOCAB, 8]
                  const float* __restrict__ rp,    // [8]
                  float* __restrict__ out,         // [ntok, 128]
                  int ntok)
{
    __shared__ float e_buf[NWARPS][STAGES][DIM];   // 32 KB
    __shared__ float b_buf[NWARPS][STAGES][RANK];  // 2 KB

    const int lane = threadIdx.x & 31;
    const int w    = threadIdx.x >> 5;
    const int warp_global = blockIdx.x * NWARPS + w;

    // ---- inline index-dtype detection ----
    const long long* x64 = reinterpret_cast<const long long*>(xv);
    const int*       x32 = reinterpret_cast<const int*>(xv);
    long long probe = x64[lane];
    bool bad = (probe < 0) || (probe >= (long long)VOCAB);
    const bool is64 = (__ballot_sync(0xFFFFFFFFu, bad) == 0u);

    // Gated+scaled A columns for this lane's 4 dims, packed as f32x2 pairs.
    uint64_t a2[RANK][2];
#pragma unroll
    for (int r = 0; r < RANK; r++) {
        float g = (rp[r] > RANK_THRESHOLD) ? SCALING : 0.0f;
        float4 av = reinterpret_cast<const float4*>(A)[r * (DIM / 4) + lane];
        a2[r][0] = pack2(av.x * g, av.y * g);
        a2[r][1] = pack2(av.z * g, av.w * g);
    }

    const int base = warp_global * CHUNK;
    if (base >= ntok) return;
    const int tend = min(base + CHUNK, ntok);
    const int nt = tend - base;

    const uint32_t e_base = (uint32_t)__cvta_generic_to_shared(&e_buf[w][0][0]);
    const uint32_t b_base = (uint32_t)__cvta_generic_to_shared(&b_buf[w][0][0]);

    // ---------------- prologue: fill pipeline ----------------
#pragma unroll
    for (int s = 0; s < STAGES; s++) {
        int t = base + s;
        if (t < tend) {
            uint32_t idx = is64 ? (uint32_t)x64[t] : (uint32_t)x32[t];
            cp_async16(e_base + (uint32_t)(s * DIM + lane * 4) * 4,
                       E + (size_t)idx * DIM + lane * 4);
            if (lane < 2)
                cp_async16(b_base + (uint32_t)(s * RANK + lane * 4) * 4,
                           Bm + (size_t)idx * RANK + lane * 4);
        }
        cp_commit();
    }

    // ---------------- steady state ----------------
    for (int i = 0; i < nt; i++) {
        asm volatile("cp.async.wait_group %0;\n" :: "n"(STAGES - 1));
        __syncwarp();   // make lanes 0/1's B copies visible to all lanes

        const int s = i & (STAGES - 1);
        float4 e  = *reinterpret_cast<const float4*>(&e_buf[w][s][lane * 4]);
        float4 b0 = *reinterpret_cast<const float4*>(&b_buf[w][s][0]);
        float4 b1 = *reinterpret_cast<const float4*>(&b_buf[w][s][4]);

        __syncwarp();   // all lanes done reading stage s before refill

        int t = base + i + STAGES;
        if (t < tend) {
            uint32_t idx = is64 ? (uint32_t)x64[t] : (uint32_t)x32[t];
            cp_async16(e_base + (uint32_t)(s * DIM + lane * 4) * 4,
                       E + (size_t)idx * DIM + lane * 4);
            if (lane < 2)
                cp_async16(b_base + (uint32_t)(s * RANK + lane * 4) * 4,
                           Bm + (size_t)idx * RANK + lane * 4);
        }
        cp_commit();

        // packed f32x2 math: 16 FFMA2 + 8 broadcasts instead of 32 FFMA
        uint64_t o0 = pack2(e.x, e.y);
        uint64_t o1 = pack2(e.z, e.w);
        uint64_t bb;
        bb = bcast2(b0.x); o0 = fma2(bb, a2[0][0], o0); o1 = fma2(bb, a2[0][1], o1);
        bb = bcast2(b0.y); o0 = fma2(bb, a2[1][0], o0); o1 = fma2(bb, a2[1][1], o1);
        bb = bcast2(b0.z); o0 = fma2(bb, a2[2][0], o0); o1 = fma2(bb, a2[2][1], o1);
        bb = bcast2(b0.w); o0 = fma2(bb, a2[3][0], o0); o1 = fma2(bb, a2[3][1], o1);
        bb = bcast2(b1.x); o0 = fma2(bb, a2[4][0], o0); o1 = fma2(bb, a2[4][1], o1);
        bb = bcast2(b1.y); o0 = fma2(bb, a2[5][0], o0); o1 = fma2(bb, a2[5][1], o1);
        bb = bcast2(b1.z); o0 = fma2(bb, a2[6][0], o0); o1 = fma2(bb, a2[6][1], o1);
        bb = bcast2(b1.w); o0 = fma2(bb, a2[7][0], o0); o1 = fma2(bb, a2[7][1], o1);

        float4 o;
        unpack2(o0, o.x, o.y);
        unpack2(o1, o.z, o.w);

        __stcs(reinterpret_cast<float4*>(out + (size_t)(base + i) * DIM) + lane, o);
    }
}

extern "C" void kernel_launch(void* const* d_in, const int* in_sizes, int n_in,
                              void* d_out, int out_size)
{
    const void*  x  = d_in[0];                // [B, L] int32 or int64
    const float* E  = (const float*)d_in[1];  // [VOCAB, 128]
    const float* A  = (const float*)d_in[2];  // [8, 128]
    const float* Bm = (const float*)d_in[3];  // [VOCAB, 8]
    const float* rp = (const float*)d_in[4];  // [8]
    float* out = (float*)d_out;

    const int ntok = out_size / DIM;

    const int tok_per_block = NWARPS * CHUNK;                // 256
    int blocks = (ntok + tok_per_block - 1) / tok_per_block; // 3200
    cora_embed_kernel<<<blocks, NWARPS * 32>>>(x, E, A, Bm, rp, out, ntok);
}

// round 16
// speedup vs baseline: 1.1958x; 1.0289x over previous
#include <cuda_runtime.h>
#include <cuda_bf16.h>
#include <cstdint>

#define VOCAB 500000
#define DIM 128
#define RANK 8
#define SCALING 2.0f
#define RANK_THRESHOLD 0.1f

#define NWARPS 8          // warps per block (256 threads)
#define STAGES 8          // cp.async pipeline depth (tokens in flight per warp)
#define CHUNK 16          // tokens per warp chunk (minimal CTA lifetime / tail drain)

__device__ __forceinline__ void cp_async16(uint32_t smem_addr, const void* gptr) {
    asm volatile("cp.async.cg.shared.global [%0], [%1], 16;\n"
                 :: "r"(smem_addr), "l"(gptr));
}
__device__ __forceinline__ void cp_commit() {
    asm volatile("cp.async.commit_group;\n");
}

// ---- packed f32x2 helpers (FFMA2 is only reachable via PTX fma.rn.f32x2) ----
__device__ __forceinline__ uint64_t pack2(float lo, float hi) {
    uint64_t r; asm("mov.b64 %0, {%1, %2};" : "=l"(r) : "f"(lo), "f"(hi)); return r;
}
__device__ __forceinline__ uint64_t bcast2(float v) {
    uint64_t r; asm("mov.b64 %0, {%1, %1};" : "=l"(r) : "f"(v)); return r;
}
__device__ __forceinline__ uint64_t fma2(uint64_t a, uint64_t b, uint64_t c) {
    uint64_t d; asm("fma.rn.f32x2 %0, %1, %2, %3;" : "=l"(d) : "l"(a), "l"(b), "l"(c)); return d;
}
__device__ __forceinline__ void unpack2(uint64_t v, float& lo, float& hi) {
    asm("mov.b64 {%0, %1}, %2;" : "=f"(lo), "=f"(hi) : "l"(v));
}

__global__ void __launch_bounds__(NWARPS * 32)
cora_embed_kernel(const void* __restrict__ xv,
                  const float* __restrict__ E,     // [VOCAB, 128]
                  const float* __restrict__ A,     // [8, 128]
                  const float* __restrict__ Bm,    // [VOCAB, 8]
                  const float* __restrict__ rp,    // [8]
                  float* __restrict__ out,         // [ntok, 128]
                  int ntok)
{
    __shared__ float e_buf[NWARPS][STAGES][DIM];   // 32 KB
    __shared__ float b_buf[NWARPS][STAGES][RANK];  // 2 KB

    const int lane = threadIdx.x & 31;
    const int w    = threadIdx.x >> 5;
    const int warp_global = blockIdx.x * NWARPS + w;

    // ---- inline index-dtype detection ----
    const long long* x64 = reinterpret_cast<const long long*>(xv);
    const int*       x32 = reinterpret_cast<const int*>(xv);
    long long probe = x64[lane];
    bool bad = (probe < 0) || (probe >= (long long)VOCAB);
    const bool is64 = (__ballot_sync(0xFFFFFFFFu, bad) == 0u);

    // Gated+scaled A columns for this lane's 4 dims, packed as f32x2 pairs.
    uint64_t a2[RANK][2];
#pragma unroll
    for (int r = 0; r < RANK; r++) {
        float g = (rp[r] > RANK_THRESHOLD) ? SCALING : 0.0f;
        float4 av = reinterpret_cast<const float4*>(A)[r * (DIM / 4) + lane];
        a2[r][0] = pack2(av.x * g, av.y * g);
        a2[r][1] = pack2(av.z * g, av.w * g);
    }

    const int base = warp_global * CHUNK;
    if (base >= ntok) return;
    const int tend = min(base + CHUNK, ntok);
    const int nt = tend - base;

    const uint32_t e_base = (uint32_t)__cvta_generic_to_shared(&e_buf[w][0][0]);
    const uint32_t b_base = (uint32_t)__cvta_generic_to_shared(&b_buf[w][0][0]);

    // ---------------- prologue: fill pipeline ----------------
#pragma unroll
    for (int s = 0; s < STAGES; s++) {
        int t = base + s;
        if (t < tend) {
            uint32_t idx = is64 ? (uint32_t)x64[t] : (uint32_t)x32[t];
            cp_async16(e_base + (uint32_t)(s * DIM + lane * 4) * 4,
                       E + (size_t)idx * DIM + lane * 4);
            if (lane < 2)
                cp_async16(b_base + (uint32_t)(s * RANK + lane * 4) * 4,
                           Bm + (size_t)idx * RANK + lane * 4);
        }
        cp_commit();
    }

    // ---------------- steady state ----------------
    for (int i = 0; i < nt; i++) {
        asm volatile("cp.async.wait_group %0;\n" :: "n"(STAGES - 1));
        __syncwarp();   // make lanes 0/1's B copies visible to all lanes

        const int s = i & (STAGES - 1);
        float4 e  = *reinterpret_cast<const float4*>(&e_buf[w][s][lane * 4]);
        float4 b0 = *reinterpret_cast<const float4*>(&b_buf[w][s][0]);
        float4 b1 = *reinterpret_cast<const float4*>(&b_buf[w][s][4]);

        __syncwarp();   // all lanes done reading stage s before refill

        int t = base + i + STAGES;
        if (t < tend) {
            uint32_t idx = is64 ? (uint32_t)x64[t] : (uint32_t)x32[t];
            cp_async16(e_base + (uint32_t)(s * DIM + lane * 4) * 4,
                       E + (size_t)idx * DIM + lane * 4);
            if (lane < 2)
                cp_async16(b_base + (uint32_t)(s * RANK + lane * 4) * 4,
                           Bm + (size_t)idx * RANK + lane * 4);
        }
        cp_commit();

        // packed f32x2 math: 16 FFMA2 + 8 broadcasts instead of 32 FFMA
        uint64_t o0 = pack2(e.x, e.y);
        uint64_t o1 = pack2(e.z, e.w);
        uint64_t bb;
        bb = bcast2(b0.x); o0 = fma2(bb, a2[0][0], o0); o1 = fma2(bb, a2[0][1], o1);
        bb = bcast2(b0.y); o0 = fma2(bb, a2[1][0], o0); o1 = fma2(bb, a2[1][1], o1);
        bb = bcast2(b0.z); o0 = fma2(bb, a2[2][0], o0); o1 = fma2(bb, a2[2][1], o1);
        bb = bcast2(b0.w); o0 = fma2(bb, a2[3][0], o0); o1 = fma2(bb, a2[3][1], o1);
        bb = bcast2(b1.x); o0 = fma2(bb, a2[4][0], o0); o1 = fma2(bb, a2[4][1], o1);
        bb = bcast2(b1.y); o0 = fma2(bb, a2[5][0], o0); o1 = fma2(bb, a2[5][1], o1);
        bb = bcast2(b1.z); o0 = fma2(bb, a2[6][0], o0); o1 = fma2(bb, a2[6][1], o1);
        bb = bcast2(b1.w); o0 = fma2(bb, a2[7][0], o0); o1 = fma2(bb, a2[7][1], o1);

        float4 o;
        unpack2(o0, o.x, o.y);
        unpack2(o1, o.z, o.w);

        __stcs(reinterpret_cast<float4*>(out + (size_t)(base + i) * DIM) + lane, o);
    }
}

extern "C" void kernel_launch(void* const* d_in, const int* in_sizes, int n_in,
                              void* d_out, int out_size)
{
    const void*  x  = d_in[0];                // [B, L] int32 or int64
    const float* E  = (const float*)d_in[1];  // [VOCAB, 128]
    const float* A  = (const float*)d_in[2];  // [8, 128]
    const float* Bm = (const float*)d_in[3];  // [VOCAB, 8]
    const float* rp = (const float*)d_in[4];  // [8]
    float* out = (float*)d_out;

    const int ntok = out_size / DIM;

    const int tok_per_block = NWARPS * CHUNK;                // 128
    int blocks = (ntok + tok_per_block - 1) / tok_per_block; // 6400
    cora_embed_kernel<<<blocks, NWARPS * 32>>>(x, E, A, Bm, rp, out, ntok);
}